// round 11
// baseline (speedup 1.0000x reference)
#include <cuda_runtime.h>
#include <cstdint>

#define HDIM 4096
#define EXP  64
#define BM   128
#define BN   64
#define BK   16
#define NCH  (HDIM / BK)   // 256
#define GCAP 8192

typedef unsigned long long ull;

// ---------------------------------------------------------------------------
// Device globals
// ---------------------------------------------------------------------------
__device__ float    g_thresh[EXP];
__device__ unsigned g_hist0[EXP * 64];
__device__ unsigned g_b0[EXP];
__device__ unsigned g_remk[EXP];
__device__ int      g_cand_n[EXP];
__device__ unsigned g_cand[EXP][GCAP];
__device__ unsigned g_cand2[EXP][GCAP];

__device__ __forceinline__ unsigned sortable(float f) {
    unsigned u = __float_as_uint(f);
    return u ^ ((u & 0x80000000u) ? 0xFFFFFFFFu : 0x80000000u);
}
__device__ __forceinline__ ull dup2(float f) {
    ull r;
    asm("mov.b64 %0, {%1, %1};" : "=l"(r) : "r"(__float_as_uint(f)));
    return r;
}

// ---------------------------------------------------------------------------
// Kernel 1: logits[N,64] = x[N,4096] @ W[4096,64], exact fp32.
// Per-output accumulation: sequential k-ascending FFMA chain (one FFMA2 lane
// per output) — bit-identical to the R1 kernel that passed.
// Inner step: 6x LDS.128 + 32x FFMA2, zero movs.
// ---------------------------------------------------------------------------
__global__ __launch_bounds__(128, 4) void gemm_kernel(const float* __restrict__ x,
                                                      const float* __restrict__ W,
                                                      float* __restrict__ logits) {
    __shared__ float xs[2][BK][132];   // [buf][k][row], pitch 132 floats
    __shared__ ull   wsd[2][BK][BN];   // [buf][k][col] duplicated (w,w)

    const int tid  = threadIdx.x;
    const int row0 = blockIdx.x * BM;
    const int rg   = tid >> 3;    // rows rg*8 .. +7
    const int cg   = tid & 7;     // cols cg*8 .. +7

    // x staging map: 4 tasks; task it -> row (tid>>2)+it*32, k-seg (tid&3)*4
    const int xrow = tid >> 2;
    const int xk4  = (tid & 3) * 4;
    const float* xptr = x + (size_t)(row0 + xrow) * HDIM + xk4;
    // W staging map: 2 tasks; task i -> k-row (tid>>4)+i*8, cols (tid&15)*4..+3
    const int wkr = tid >> 4;
    const int wc4 = (tid & 15) * 4;
    const float* wptr = W + (size_t)wkr * EXP + wc4;

    ull acc[4][8];   // [row-pair i][col j]; lanes = rows (rg*8+2i, +1)
#pragma unroll
    for (int i = 0; i < 4; ++i)
#pragma unroll
        for (int j = 0; j < 8; ++j) acc[i][j] = 0ULL;

    float4 xv[4], wv[2];
    // ---- load chunk 0 ----
#pragma unroll
    for (int it = 0; it < 4; ++it) xv[it] = *(const float4*)(xptr + (size_t)it * 32 * HDIM);
#pragma unroll
    for (int i = 0; i < 2; ++i)    wv[i]  = *(const float4*)(wptr + (size_t)i * 8 * EXP);

    // ---- stage chunk 0 into buf 0 ----
#pragma unroll
    for (int it = 0; it < 4; ++it) {
        xs[0][xk4 + 0][xrow + it * 32] = xv[it].x;
        xs[0][xk4 + 1][xrow + it * 32] = xv[it].y;
        xs[0][xk4 + 2][xrow + it * 32] = xv[it].z;
        xs[0][xk4 + 3][xrow + it * 32] = xv[it].w;
    }
#pragma unroll
    for (int i = 0; i < 2; ++i) {
        wsd[0][wkr + i * 8][wc4 + 0] = dup2(wv[i].x);
        wsd[0][wkr + i * 8][wc4 + 1] = dup2(wv[i].y);
        wsd[0][wkr + i * 8][wc4 + 2] = dup2(wv[i].z);
        wsd[0][wkr + i * 8][wc4 + 3] = dup2(wv[i].w);
    }
    __syncthreads();

    for (int c = 0; c < NCH; ++c) {
        const int buf = c & 1;
        // prefetch next chunk into regs (latency overlapped with compute)
        if (c + 1 < NCH) {
            const int k0 = (c + 1) * BK;
#pragma unroll
            for (int it = 0; it < 4; ++it)
                xv[it] = *(const float4*)(xptr + (size_t)it * 32 * HDIM + k0);
#pragma unroll
            for (int i = 0; i < 2; ++i)
                wv[i] = *(const float4*)(wptr + (size_t)(k0 + i * 8) * EXP);
        }
        // ---- compute 16 k's ----
#pragma unroll
        for (int k = 0; k < BK; ++k) {
            const float* ap = &xs[buf][k][rg * 8];
            ulonglong2 a01 = *(const ulonglong2*)ap;
            ulonglong2 a23 = *(const ulonglong2*)(ap + 4);
            ull a2[4] = {a01.x, a01.y, a23.x, a23.y};
            const ulonglong2* bp = (const ulonglong2*)&wsd[buf][k][cg * 8];
            ull b2[8];
#pragma unroll
            for (int j2 = 0; j2 < 4; ++j2) {
                ulonglong2 q = bp[j2];
                b2[2 * j2] = q.x; b2[2 * j2 + 1] = q.y;
            }
#pragma unroll
            for (int i = 0; i < 4; ++i)
#pragma unroll
                for (int j = 0; j < 8; ++j)
                    asm("fma.rn.f32x2 %0, %1, %2, %0;"
                        : "+l"(acc[i][j]) : "l"(a2[i]), "l"(b2[j]));
        }
        // ---- stage next chunk into other buffer ----
        if (c + 1 < NCH) {
            const int nb = buf ^ 1;
#pragma unroll
            for (int it = 0; it < 4; ++it) {
                xs[nb][xk4 + 0][xrow + it * 32] = xv[it].x;
                xs[nb][xk4 + 1][xrow + it * 32] = xv[it].y;
                xs[nb][xk4 + 2][xrow + it * 32] = xv[it].z;
                xs[nb][xk4 + 3][xrow + it * 32] = xv[it].w;
            }
#pragma unroll
            for (int i = 0; i < 2; ++i) {
                wsd[nb][wkr + i * 8][wc4 + 0] = dup2(wv[i].x);
                wsd[nb][wkr + i * 8][wc4 + 1] = dup2(wv[i].y);
                wsd[nb][wkr + i * 8][wc4 + 2] = dup2(wv[i].z);
                wsd[nb][wkr + i * 8][wc4 + 3] = dup2(wv[i].w);
            }
        }
        __syncthreads();
    }

    // ---- writeback: 8 rows x 8 cols per thread ----
#pragma unroll
    for (int i = 0; i < 4; ++i) {
        float lo[8], hi[8];
#pragma unroll
        for (int j = 0; j < 8; ++j) {
            lo[j] = __uint_as_float((unsigned)(acc[i][j] & 0xFFFFFFFFULL));
            hi[j] = __uint_as_float((unsigned)(acc[i][j] >> 32));
        }
        float* p0 = logits + (size_t)(row0 + rg * 8 + 2 * i) * EXP + cg * 8;
        float* p1 = p0 + EXP;
        *(float4*)p0       = make_float4(lo[0], lo[1], lo[2], lo[3]);
        *(float4*)(p0 + 4) = make_float4(lo[4], lo[5], lo[6], lo[7]);
        *(float4*)p1       = make_float4(hi[0], hi[1], hi[2], hi[3]);
        *(float4*)(p1 + 4) = make_float4(hi[4], hi[5], hi[6], hi[7]);
    }
}

// ---------------------------------------------------------------------------
// Kernel 2: fused row-major top-6-bit histograms for all 64 experts
// ---------------------------------------------------------------------------
__global__ __launch_bounds__(256) void hist0_kernel(const float* __restrict__ logits) {
    __shared__ unsigned h[EXP * 64];
    for (int i = threadIdx.x; i < EXP * 64; i += 256) h[i] = 0;
    __syncthreads();
    const int row0 = blockIdx.x * 128;
#pragma unroll
    for (int j = 0; j < 8; ++j) {
        int u = threadIdx.x + j * 256;
        int r = u >> 4, cgq = u & 15;
        float4 v = *(const float4*)(logits + (size_t)(row0 + r) * EXP + cgq * 4);
        float vv[4] = {v.x, v.y, v.z, v.w};
#pragma unroll
        for (int m = 0; m < 4; ++m)
            atomicAdd(&h[(cgq * 4 + m) * 64 + (sortable(vv[m]) >> 26)], 1u);
    }
    __syncthreads();
    for (int i = threadIdx.x; i < EXP * 64; i += 256) {
        unsigned c = h[i];
        if (c) atomicAdd(&g_hist0[i], c);
    }
}

// ---------------------------------------------------------------------------
// Kernel 3: pick top bucket + residual k per expert
// ---------------------------------------------------------------------------
__global__ void bucket_kernel(int k) {
    int e = threadIdx.x;   // 64 threads
    unsigned remk = (unsigned)k, cum = 0;
    int b = 63;
    for (; b > 0; --b) {
        unsigned h = g_hist0[e * 64 + b];
        if (cum + h >= remk) break;
        cum += h;
    }
    g_b0[e]   = (unsigned)b;
    g_remk[e] = remk - cum;
}

// ---------------------------------------------------------------------------
// Kernel 4: coalesced gather of bucket candidates (one float4 per thread)
// ---------------------------------------------------------------------------
__global__ __launch_bounds__(256) void gather_kernel(const float* __restrict__ logits,
                                                     int total4) {
    __shared__ unsigned sb0[EXP];
    if (threadIdx.x < EXP) sb0[threadIdx.x] = g_b0[threadIdx.x];
    __syncthreads();
    int idx = blockIdx.x * 256 + threadIdx.x;
    if (idx >= total4) return;
    int q = idx & 15;
    float4 v = ((const float4*)logits)[idx];
    float vv[4] = {v.x, v.y, v.z, v.w};
#pragma unroll
    for (int m = 0; m < 4; ++m) {
        int e = q * 4 + m;
        unsigned u = sortable(vv[m]);
        if ((u >> 26) == sb0[e]) {
            int i = atomicAdd(&g_cand_n[e], 1);
            if (i < GCAP) g_cand[e][i] = u;
        }
    }
}

// ---------------------------------------------------------------------------
// Kernel 5: per-expert k-th largest. Local radix on gathered candidates;
// full-column scanning fallback if the bucket overflowed GCAP.
// ---------------------------------------------------------------------------
__global__ __launch_bounds__(256) void selectf_kernel(const float* __restrict__ logits,
                                                      int N) {
    __shared__ unsigned hist[256];
    __shared__ unsigned s_bv, s_remk, s_prefix, s_n2;
    const int e   = blockIdx.x;
    const int tid = threadIdx.x;
    const unsigned b0 = g_b0[e];
    const int cn = g_cand_n[e];
    const int SH[4] = {18, 10, 2, 0};
    const unsigned MK[4] = {255, 255, 255, 3};

    if (tid == 0) { s_remk = g_remk[e]; s_prefix = 0; }
    __syncthreads();

    if (cn <= GCAP) {
        unsigned* cur = g_cand[e];
        unsigned* alt = g_cand2[e];
        int n = cn;
        for (int p = 0; p < 4; ++p) {
            const int sh = SH[p]; const unsigned mk = MK[p];
            hist[tid] = 0;
            __syncthreads();
            for (int j = tid; j < n; j += 256) atomicAdd(&hist[(cur[j] >> sh) & mk], 1u);
            __syncthreads();
            if (tid == 0) {
                unsigned remk = s_remk, cum = 0;
                int b = (int)mk;
                for (; b > 0; --b) { unsigned h = hist[b]; if (cum + h >= remk) break; cum += h; }
                s_bv = (unsigned)b; s_remk = remk - cum;
                s_prefix |= ((unsigned)b) << sh; s_n2 = 0;
            }
            __syncthreads();
            if (p < 3) {
                unsigned bv = s_bv;
                for (int j = tid; j < n; j += 256) {
                    unsigned key = cur[j];
                    if (((key >> sh) & mk) == bv) { unsigned q = atomicAdd(&s_n2, 1u); alt[q] = key; }
                }
                __syncthreads();
                n = (int)s_n2;
                unsigned* tmp = cur; cur = alt; alt = tmp;
            }
        }
        if (tid == 0) {
            unsigned key = (b0 << 26) | s_prefix;
            unsigned bits = (key & 0x80000000u) ? (key ^ 0x80000000u) : ~key;
            g_thresh[e] = __uint_as_float(bits);
        }
    } else {
        unsigned pmask = 0xFC000000u;
        if (tid == 0) s_prefix = b0 << 26;
        __syncthreads();
        for (int p = 0; p < 4; ++p) {
            const int sh = SH[p]; const unsigned mk = MK[p];
            hist[tid] = 0;
            __syncthreads();
            const unsigned pre = s_prefix;
            for (int i = tid; i < N; i += 256) {
                unsigned u = sortable(logits[(size_t)i * EXP + e]);
                if ((u & pmask) == pre) atomicAdd(&hist[(u >> sh) & mk], 1u);
            }
            __syncthreads();
            if (tid == 0) {
                unsigned remk = s_remk, cum = 0;
                int b = (int)mk;
                for (; b > 0; --b) { unsigned h = hist[b]; if (cum + h >= remk) break; cum += h; }
                s_prefix = pre | (((unsigned)b) << sh); s_remk = remk - cum;
            }
            pmask |= mk << sh;
            __syncthreads();
        }
        if (tid == 0) {
            unsigned key = s_prefix;
            unsigned bits = (key & 0x80000000u) ? (key ^ 0x80000000u) : ~key;
            g_thresh[e] = __uint_as_float(bits);
        }
    }
}

// ---------------------------------------------------------------------------
// Kernel 6: conflict resolution + fallback argmax. One warp per token.
// ---------------------------------------------------------------------------
__global__ __launch_bounds__(256) void assign_kernel(const float* __restrict__ logits,
                                                     float* __restrict__ out_w,
                                                     float* __restrict__ out_i,
                                                     int N) {
    const int gwarp = (int)((blockIdx.x * (size_t)blockDim.x + threadIdx.x) >> 5);
    const int lane  = threadIdx.x & 31;
    if (gwarp >= N) return;

    const float NEG_INF = __int_as_float(0xff800000);
    float2 v = *(const float2*)(logits + (size_t)gwarp * EXP + lane * 2);
    float t0 = g_thresh[lane * 2];
    float t1 = g_thresh[lane * 2 + 1];

    float cs = NEG_INF; int ci = 127;                  // claimed best
    if (v.x >= t0)             { cs = v.x; ci = lane * 2; }
    if (v.y >= t1 && v.y > cs) { cs = v.y; ci = lane * 2 + 1; }

    float fs = v.x; int fi = lane * 2;                 // fallback argmax
    if (v.y > fs) { fs = v.y; fi = lane * 2 + 1; }

#pragma unroll
    for (int off = 16; off; off >>= 1) {
        float os = __shfl_xor_sync(0xFFFFFFFFu, cs, off);
        int   oi = __shfl_xor_sync(0xFFFFFFFFu, ci, off);
        if (os > cs || (os == cs && oi < ci)) { cs = os; ci = oi; }
        float ofs = __shfl_xor_sync(0xFFFFFFFFu, fs, off);
        int   ofi = __shfl_xor_sync(0xFFFFFFFFu, fi, off);
        if (ofs > fs || (ofs == fs && ofi < fi)) { fs = ofs; fi = ofi; }
    }

    if (lane == 0) {
        float w; int e;
        if (ci < EXP) { w = cs; e = ci; }
        else          { w = fs; e = fi; }
        out_w[gwarp] = w;
        out_i[gwarp] = (float)e;
    }
}

// ---------------------------------------------------------------------------
// Output layout: [0,N) weights | [N,2N) indices (float) | [2N, 2N+N*E) logits
// ---------------------------------------------------------------------------
extern "C" void kernel_launch(void* const* d_in, const int* in_sizes, int n_in,
                              void* d_out, int out_size) {
    const float* x = (const float*)d_in[0];
    const float* W = (const float*)d_in[1];
    const int N = in_sizes[0] / HDIM;   // 32768

    float* out    = (float*)d_out;
    float* out_w  = out;
    float* out_i  = out + N;
    float* logits = out + 2 * (size_t)N;

    int k = N / EXP;
    if (k < 1) k = 1;
    if (k > N) k = N;

    void* p;
    cudaGetSymbolAddress(&p, g_hist0);  cudaMemsetAsync(p, 0, EXP * 64 * sizeof(unsigned));
    cudaGetSymbolAddress(&p, g_cand_n); cudaMemsetAsync(p, 0, EXP * sizeof(int));

    gemm_kernel<<<N / BM, 128>>>(x, W, logits);
    hist0_kernel<<<N / 128, 256>>>(logits);
    bucket_kernel<<<1, 64>>>(k);
    const int total4 = N * 16;
    gather_kernel<<<(total4 + 255) / 256, 256>>>(logits, total4);
    selectf_kernel<<<EXP, 256>>>(logits, N);
    assign_kernel<<<(int)(((size_t)N * 32 + 255) / 256), 256>>>(logits, out_w, out_i, N);
}

// round 12
// speedup vs baseline: 2.5579x; 2.5579x over previous
#include <cuda_runtime.h>
#include <cstdint>

#define HDIM 4096
#define EXP  64
#define BM   128
#define BK   32
#define GCAP 8192

typedef unsigned long long ull;

// ---------------------------------------------------------------------------
// Device globals
// ---------------------------------------------------------------------------
__device__ float    g_thresh[EXP];
__device__ unsigned g_hist0[EXP * 64];
__device__ unsigned g_b0[EXP];
__device__ unsigned g_remk[EXP];
__device__ int      g_cand_n[EXP];
__device__ unsigned g_cand[EXP][GCAP];
__device__ unsigned g_cand2[EXP][GCAP];

__device__ __forceinline__ unsigned sortable(float f) {
    unsigned u = __float_as_uint(f);
    return u ^ ((u & 0x80000000u) ? 0xFFFFFFFFu : 0x80000000u);
}

// ---------------------------------------------------------------------------
// Kernel 1: logits[N,64] = x[N,4096] @ W[4096,64], exact fp32 accumulate.
// (R1 kernel verbatim — 453us measured — plus __launch_bounds__(256,3) for
//  3 CTAs/SM instead of 2. Same instruction stream, bit-identical results.)
// ---------------------------------------------------------------------------
__global__ __launch_bounds__(256, 3) void gemm_kernel(const float* __restrict__ x,
                                                      const float* __restrict__ W,
                                                      float* __restrict__ logits) {
    __shared__ float xs[BK][BM + 2];   // k-major x tile (row pairs contiguous)
    __shared__ float ws[BK][EXP];

    const int tid  = threadIdx.x;
    const int row0 = blockIdx.x * BM;
    const int cg   = tid & 15;   // cols cg*4 .. cg*4+3
    const int rg   = tid >> 4;   // rows rg*8 .. rg*8+7

    ull acc[4][4];  // [col j][row-pair ip]; lanes = (row 2ip, row 2ip+1)
#pragma unroll
    for (int j = 0; j < 4; ++j)
#pragma unroll
        for (int ip = 0; ip < 4; ++ip) acc[j][ip] = 0ULL;

    const int lr = tid >> 3;          // load row within 32-row pass
    const int lc = (tid & 7) * 4;     // load col (float4)

    for (int k0 = 0; k0 < HDIM; k0 += BK) {
        // stage x tile [BM x BK] -> xs[k][row]
#pragma unroll
        for (int p = 0; p < 4; ++p) {
            int r = lr + p * 32;
            float4 v = *(const float4*)(x + (size_t)(row0 + r) * HDIM + k0 + lc);
            xs[lc + 0][r] = v.x; xs[lc + 1][r] = v.y;
            xs[lc + 2][r] = v.z; xs[lc + 3][r] = v.w;
        }
        // stage W tile [BK x 64]
#pragma unroll
        for (int p = 0; p < 2; ++p) {
            int idx = tid + p * 256;
            int r = idx >> 4;
            int c = (idx & 15) * 4;
            *(float4*)&ws[r][c] = *(const float4*)(W + (size_t)(k0 + r) * EXP + c);
        }
        __syncthreads();

#pragma unroll
        for (int k = 0; k < BK; ++k) {
            float4 bv = *(const float4*)&ws[k][cg * 4];
            ull b2[4];
            asm("mov.b64 %0, {%1, %1};" : "=l"(b2[0]) : "r"(__float_as_uint(bv.x)));
            asm("mov.b64 %0, {%1, %1};" : "=l"(b2[1]) : "r"(__float_as_uint(bv.y)));
            asm("mov.b64 %0, {%1, %1};" : "=l"(b2[2]) : "r"(__float_as_uint(bv.z)));
            asm("mov.b64 %0, {%1, %1};" : "=l"(b2[3]) : "r"(__float_as_uint(bv.w)));
            ull a2[4];
#pragma unroll
            for (int ip = 0; ip < 4; ++ip)
                a2[ip] = *(const ull*)&xs[k][rg * 8 + ip * 2];
#pragma unroll
            for (int j = 0; j < 4; ++j)
#pragma unroll
                for (int ip = 0; ip < 4; ++ip)
                    asm("fma.rn.f32x2 %0, %1, %2, %0;"
                        : "+l"(acc[j][ip]) : "l"(a2[ip]), "l"(b2[j]));
        }
        __syncthreads();
    }

    // writeback: 8 rows x 4 cols per thread, float4 per row
#pragma unroll
    for (int ip = 0; ip < 4; ++ip) {
        float lo[4], hi[4];
#pragma unroll
        for (int j = 0; j < 4; ++j) {
            lo[j] = __uint_as_float((unsigned)(acc[j][ip] & 0xFFFFFFFFULL));
            hi[j] = __uint_as_float((unsigned)(acc[j][ip] >> 32));
        }
        int r = row0 + rg * 8 + ip * 2;
        *(float4*)(logits + (size_t)r * EXP + cg * 4) =
            make_float4(lo[0], lo[1], lo[2], lo[3]);
        *(float4*)(logits + (size_t)(r + 1) * EXP + cg * 4) =
            make_float4(hi[0], hi[1], hi[2], hi[3]);
    }
}

// ---------------------------------------------------------------------------
// Kernel 2: fused row-major top-6-bit histograms for all 64 experts
// ---------------------------------------------------------------------------
__global__ __launch_bounds__(256) void hist0_kernel(const float* __restrict__ logits) {
    __shared__ unsigned h[EXP * 64];
    for (int i = threadIdx.x; i < EXP * 64; i += 256) h[i] = 0;
    __syncthreads();
    const int row0 = blockIdx.x * 128;
#pragma unroll
    for (int j = 0; j < 8; ++j) {
        int u = threadIdx.x + j * 256;
        int r = u >> 4, cgq = u & 15;
        float4 v = *(const float4*)(logits + (size_t)(row0 + r) * EXP + cgq * 4);
        float vv[4] = {v.x, v.y, v.z, v.w};
#pragma unroll
        for (int m = 0; m < 4; ++m)
            atomicAdd(&h[(cgq * 4 + m) * 64 + (sortable(vv[m]) >> 26)], 1u);
    }
    __syncthreads();
    for (int i = threadIdx.x; i < EXP * 64; i += 256) {
        unsigned c = h[i];
        if (c) atomicAdd(&g_hist0[i], c);
    }
}

// ---------------------------------------------------------------------------
// Kernel 3: pick top bucket + residual k per expert
// ---------------------------------------------------------------------------
__global__ void bucket_kernel(int k) {
    int e = threadIdx.x;   // 64 threads
    unsigned remk = (unsigned)k, cum = 0;
    int b = 63;
    for (; b > 0; --b) {
        unsigned h = g_hist0[e * 64 + b];
        if (cum + h >= remk) break;
        cum += h;
    }
    g_b0[e]   = (unsigned)b;
    g_remk[e] = remk - cum;
}

// ---------------------------------------------------------------------------
// Kernel 4: row-major gather of bucket candidates into per-expert lists
// ---------------------------------------------------------------------------
__global__ __launch_bounds__(256) void gather_kernel(const float* __restrict__ logits) {
    __shared__ unsigned sb0[EXP];
    if (threadIdx.x < EXP) sb0[threadIdx.x] = g_b0[threadIdx.x];
    __syncthreads();
    const int t = blockIdx.x * 256 + threadIdx.x;   // token row
    const float4* row = (const float4*)(logits + (size_t)t * EXP);
#pragma unroll
    for (int q = 0; q < 16; ++q) {
        float4 v = row[q];
        float vv[4] = {v.x, v.y, v.z, v.w};
#pragma unroll
        for (int m = 0; m < 4; ++m) {
            int e = q * 4 + m;
            unsigned u = sortable(vv[m]);
            if ((u >> 26) == sb0[e]) {
                int i = atomicAdd(&g_cand_n[e], 1);
                if (i < GCAP) g_cand[e][i] = u;
            }
        }
    }
}

// ---------------------------------------------------------------------------
// Kernel 5: per-expert k-th largest. Local radix on gathered candidates;
// full-column scanning fallback if the bucket overflowed GCAP.
// ---------------------------------------------------------------------------
__global__ __launch_bounds__(256) void selectf_kernel(const float* __restrict__ logits,
                                                      int N) {
    __shared__ unsigned hist[256];
    __shared__ unsigned s_bv, s_remk, s_prefix, s_n2;
    const int e   = blockIdx.x;
    const int tid = threadIdx.x;
    const unsigned b0 = g_b0[e];
    const int cn = g_cand_n[e];
    const int SH[4] = {18, 10, 2, 0};
    const unsigned MK[4] = {255, 255, 255, 3};

    if (tid == 0) { s_remk = g_remk[e]; s_prefix = 0; }
    __syncthreads();

    if (cn <= GCAP) {
        unsigned* cur = g_cand[e];
        unsigned* alt = g_cand2[e];
        int n = cn;
        for (int p = 0; p < 4; ++p) {
            const int sh = SH[p]; const unsigned mk = MK[p];
            hist[tid] = 0;
            __syncthreads();
            for (int j = tid; j < n; j += 256) atomicAdd(&hist[(cur[j] >> sh) & mk], 1u);
            __syncthreads();
            if (tid == 0) {
                unsigned remk = s_remk, cum = 0;
                int b = (int)mk;
                for (; b > 0; --b) { unsigned h = hist[b]; if (cum + h >= remk) break; cum += h; }
                s_bv = (unsigned)b; s_remk = remk - cum;
                s_prefix |= ((unsigned)b) << sh; s_n2 = 0;
            }
            __syncthreads();
            if (p < 3) {
                unsigned bv = s_bv;
                for (int j = tid; j < n; j += 256) {
                    unsigned key = cur[j];
                    if (((key >> sh) & mk) == bv) { unsigned q = atomicAdd(&s_n2, 1u); alt[q] = key; }
                }
                __syncthreads();
                n = (int)s_n2;
                unsigned* tmp = cur; cur = alt; alt = tmp;
            }
        }
        if (tid == 0) {
            unsigned key = (b0 << 26) | s_prefix;
            unsigned bits = (key & 0x80000000u) ? (key ^ 0x80000000u) : ~key;
            g_thresh[e] = __uint_as_float(bits);
        }
    } else {
        unsigned pmask = 0xFC000000u;
        if (tid == 0) s_prefix = b0 << 26;
        __syncthreads();
        for (int p = 0; p < 4; ++p) {
            const int sh = SH[p]; const unsigned mk = MK[p];
            hist[tid] = 0;
            __syncthreads();
            const unsigned pre = s_prefix;
            for (int i = tid; i < N; i += 256) {
                unsigned u = sortable(logits[(size_t)i * EXP + e]);
                if ((u & pmask) == pre) atomicAdd(&hist[(u >> sh) & mk], 1u);
            }
            __syncthreads();
            if (tid == 0) {
                unsigned remk = s_remk, cum = 0;
                int b = (int)mk;
                for (; b > 0; --b) { unsigned h = hist[b]; if (cum + h >= remk) break; cum += h; }
                s_prefix = pre | (((unsigned)b) << sh); s_remk = remk - cum;
            }
            pmask |= mk << sh;
            __syncthreads();
        }
        if (tid == 0) {
            unsigned key = s_prefix;
            unsigned bits = (key & 0x80000000u) ? (key ^ 0x80000000u) : ~key;
            g_thresh[e] = __uint_as_float(bits);
        }
    }
}

// ---------------------------------------------------------------------------
// Kernel 6: conflict resolution + fallback argmax. One warp per token.
// ---------------------------------------------------------------------------
__global__ __launch_bounds__(256) void assign_kernel(const float* __restrict__ logits,
                                                     float* __restrict__ out_w,
                                                     float* __restrict__ out_i,
                                                     int N) {
    const int gwarp = (int)((blockIdx.x * (size_t)blockDim.x + threadIdx.x) >> 5);
    const int lane  = threadIdx.x & 31;
    if (gwarp >= N) return;

    const float NEG_INF = __int_as_float(0xff800000);
    float2 v = *(const float2*)(logits + (size_t)gwarp * EXP + lane * 2);
    float t0 = g_thresh[lane * 2];
    float t1 = g_thresh[lane * 2 + 1];

    float cs = NEG_INF; int ci = 127;                  // claimed best
    if (v.x >= t0)             { cs = v.x; ci = lane * 2; }
    if (v.y >= t1 && v.y > cs) { cs = v.y; ci = lane * 2 + 1; }

    float fs = v.x; int fi = lane * 2;                 // fallback argmax
    if (v.y > fs) { fs = v.y; fi = lane * 2 + 1; }

#pragma unroll
    for (int off = 16; off; off >>= 1) {
        float os = __shfl_xor_sync(0xFFFFFFFFu, cs, off);
        int   oi = __shfl_xor_sync(0xFFFFFFFFu, ci, off);
        if (os > cs || (os == cs && oi < ci)) { cs = os; ci = oi; }
        float ofs = __shfl_xor_sync(0xFFFFFFFFu, fs, off);
        int   ofi = __shfl_xor_sync(0xFFFFFFFFu, fi, off);
        if (ofs > fs || (ofs == fs && ofi < fi)) { fs = ofs; fi = ofi; }
    }

    if (lane == 0) {
        float w; int e;
        if (ci < EXP) { w = cs; e = ci; }
        else          { w = fs; e = fi; }
        out_w[gwarp] = w;
        out_i[gwarp] = (float)e;
    }
}

// ---------------------------------------------------------------------------
// Output layout: [0,N) weights | [N,2N) indices (float) | [2N, 2N+N*E) logits
// ---------------------------------------------------------------------------
extern "C" void kernel_launch(void* const* d_in, const int* in_sizes, int n_in,
                              void* d_out, int out_size) {
    const float* x = (const float*)d_in[0];
    const float* W = (const float*)d_in[1];
    const int N = in_sizes[0] / HDIM;   // 32768

    float* out    = (float*)d_out;
    float* out_w  = out;
    float* out_i  = out + N;
    float* logits = out + 2 * (size_t)N;

    int k = N / EXP;
    if (k < 1) k = 1;
    if (k > N) k = N;

    void* p;
    cudaGetSymbolAddress(&p, g_hist0);  cudaMemsetAsync(p, 0, EXP * 64 * sizeof(unsigned));
    cudaGetSymbolAddress(&p, g_cand_n); cudaMemsetAsync(p, 0, EXP * sizeof(int));

    gemm_kernel<<<N / BM, 256>>>(x, W, logits);
    hist0_kernel<<<N / 128, 256>>>(logits);
    bucket_kernel<<<1, 64>>>(k);
    gather_kernel<<<N / 256, 256>>>(logits);
    selectf_kernel<<<EXP, 256>>>(logits, N);
    assign_kernel<<<(int)(((size_t)N * 32 + 255) / 256), 256>>>(logits, out_w, out_i, N);
}